// round 15
// baseline (speedup 1.0000x reference)
#include <cuda_runtime.h>
#include <cstdint>

#define MQ   2048
#define VT   50257
#define D    4096
#define NT   256
#define GQ   8                 // queries per block
#define PERT 16                // D / NT
#define NWARP (NT / 32)
#define MARGIN 1.0e-4f         // >> 2e-6 fp32 tree-reduction error bound
#define KC   16

// Single self-contained kernel: no device globals, no intermediates.
__global__ __launch_bounds__(NT) void lp_probe(
    const float* __restrict__ E, const float* __restrict__ Tm, float* __restrict__ out)
{
    __shared__ float  sred[NWARP][12];     // fp32 reduce staging (9 used)
    __shared__ double sdd[NWARP][2];       // fp64 reduce staging
    __shared__ double s_en[GQ];            // fp64 e-norms
    __shared__ float  sbest[GQ];           // running fp32 max sim
    __shared__ int    scand[GQ][KC];
    __shared__ int    snc[GQ];
    __shared__ double gBest;
    __shared__ int    gBv;

    const int t = threadIdx.x, wid = t >> 5, lane = t & 31;
    const size_t m0 = (size_t)blockIdx.x * GQ;

    // E rows in registers (raw fp32, element d = i*NT + t)
    float er[GQ][PERT];
    #pragma unroll
    for (int q = 0; q < GQ; q++)
        #pragma unroll
        for (int i = 0; i < PERT; i++)
            er[q][i] = E[(m0 + q) * D + i * NT + t];

    // fp64 e-norms (one-time)
    for (int q = 0; q < GQ; q++) {
        double s = 0.0;
        #pragma unroll
        for (int i = 0; i < PERT; i++) s += (double)er[q][i] * (double)er[q][i];
        #pragma unroll
        for (int o = 16; o > 0; o >>= 1) s += __shfl_down_sync(0xffffffffu, s, o);
        if (lane == 0) sdd[wid][0] = s;
        __syncthreads();
        if (t == 0) {
            double tot = 0.0;
            for (int w = 0; w < NWARP; w++) tot += sdd[w][0];
            double nrm = sqrt(tot); if (nrm < 1e-8) nrm = 1e-8;
            s_en[q] = nrm;
            sbest[q] = -2.0f;
            snc[q] = 0;
        }
        __syncthreads();
    }
    // per-thread cached fp32 reciprocal norms
    float inv_en[GQ];
    #pragma unroll
    for (int q = 0; q < GQ; q++) inv_en[q] = (float)(1.0 / s_en[q]);

    // ---- two passes over the table: (A) find max, (B) collect margin band ----
    for (int pass = 0; pass < 2; pass++) {
        for (int v = 0; v < VT; v++) {
            const float* tr = Tm + (size_t)v * D;
            float acc[GQ + 1];
            #pragma unroll
            for (int q = 0; q <= GQ; q++) acc[q] = 0.0f;
            #pragma unroll
            for (int i = 0; i < PERT; i++) {
                float x = tr[i * NT + t];
                acc[GQ] = fmaf(x, x, acc[GQ]);
                #pragma unroll
                for (int q = 0; q < GQ; q++) acc[q] = fmaf(x, er[q][i], acc[q]);
            }
            #pragma unroll
            for (int q = 0; q <= GQ; q++) {
                float s = acc[q];
                #pragma unroll
                for (int o = 16; o > 0; o >>= 1) s += __shfl_down_sync(0xffffffffu, s, o);
                if (lane == 0) sred[wid][q] = s;
            }
            __syncthreads();
            if (t == 0) {
                float tn = 0.0f;
                for (int w = 0; w < NWARP; w++) tn += sred[w][GQ];
                float rtn = rsqrtf(fmaxf(tn, 1e-16f));
                #pragma unroll
                for (int q = 0; q < GQ; q++) {
                    float dot = 0.0f;
                    for (int w = 0; w < NWARP; w++) dot += sred[w][q];
                    float sim = dot * inv_en[q] * rtn;
                    if (pass == 0) {
                        if (sim > sbest[q]) sbest[q] = sim;
                    } else {
                        if (sim >= sbest[q] - MARGIN) {
                            int c = snc[q];
                            if (c < KC) { scand[q][c] = v; snc[q] = c + 1; }
                        }
                    }
                }
            }
            __syncthreads();
        }
    }

    // ---- fp64 exact rescore of candidates; lowest index wins ties ----
    for (int q = 0; q < GQ; q++) {
        const int H = min(snc[q], KC);        // H >= 1 (the max itself re-qualifies)
        if (t == 0) { gBest = -1.0e300; gBv = 0; }
        __syncthreads();
        for (int h = 0; h < H; h++) {
            const int v = scand[q][h];
            const float* tr = Tm + (size_t)v * D;
            double sd = 0.0, st = 0.0;
            #pragma unroll
            for (int i = 0; i < PERT; i++) {
                double x = (double)tr[i * NT + t];
                sd += x * (double)er[q][i];
                st += x * x;
            }
            #pragma unroll
            for (int o = 16; o > 0; o >>= 1) {
                sd += __shfl_down_sync(0xffffffffu, sd, o);
                st += __shfl_down_sync(0xffffffffu, st, o);
            }
            if (lane == 0) { sdd[wid][0] = sd; sdd[wid][1] = st; }
            __syncthreads();
            if (t == 0) {
                double td = 0.0, tt = 0.0;
                for (int w = 0; w < NWARP; w++) { td += sdd[w][0]; tt += sdd[w][1]; }
                double tn = sqrt(tt); if (tn < 1e-8) tn = 1e-8;
                double sim = td / (s_en[q] * tn);
                if (sim > gBest || (sim == gBest && v < gBv)) { gBest = sim; gBv = v; }
            }
            __syncthreads();
        }
        // THE one change this round: ids written as float32 (exact for v < 2^24)
        if (t == 0) out[m0 + q] = (float)gBv;
        __syncthreads();
    }
}

extern "C" void kernel_launch(void* const* d_in, const int* in_sizes, int n_in,
                              void* d_out, int out_size) {
    const float* A0 = (const float*)d_in[0];
    const float* A1 = (const float*)d_in[1];
    const float* E = A0; const float* T = A1;             // metadata order
    if (in_sizes[0] != MQ * D) { E = A1; T = A0; }        // size-based guard
    lp_probe<<<MQ / GQ, NT>>>(E, T, (float*)d_out);
    (void)in_sizes; (void)n_in; (void)out_size;
}

// round 16
// speedup vs baseline: 95.3313x; 95.3313x over previous
#include <cuda_runtime.h>
#include <cuda_fp16.h>
#include <mma.h>
#include <cstdint>

using namespace nvcuda;

#define M_TOTAL   2048
#define V_TOTAL   50257
#define DIM       4096
#define BM        128
#define BN        128
#define BK        32
#define APITCH    40              // halves per smem row (64B data + 16B pad)
#define V_PAD     50304           // 393 * 128
#define N_TILES   393
#define M_TILES   16
#define KCHUNKS   128             // 4096 / 32
#define MARGIN    2.5e-3f         // > worst-case fp16-input dot error (~1.5e-3)

// ----- device scratch (static; zero runtime allocation) -----
__device__ __align__(128) __half g_Ehf[(size_t)M_TOTAL * DIM];
__device__ __align__(128) __half g_Thf[(size_t)V_PAD * DIM];
__device__ __align__(128) float  g_simsf[(size_t)M_TOTAL * V_PAD];  // [m][v]
__device__ float g_enorm[M_TOTAL];
__device__ float g_tnorm[V_PAD];

// ----- kernel 1: normalize fp32 row -> unit fp16 row + fp32 norm -----
// which = 0 -> E (g_Ehf/g_enorm), which = 1 -> T (g_Thf/g_tnorm)
__global__ __launch_bounds__(256) void lp_normalize(
    const float* __restrict__ src, int n_valid, int which)
{
    __half* dstall = which ? g_Thf : g_Ehf;
    float*  norms  = which ? g_tnorm : g_enorm;
    int row = blockIdx.x, tid = threadIdx.x, wid = tid >> 5, lid = tid & 31;
    uint2* drow = reinterpret_cast<uint2*>(dstall + (size_t)row * DIM);
    __shared__ float red[8];
    if (row >= n_valid) {                 // zero padding rows
        #pragma unroll
        for (int i = 0; i < 4; i++) drow[tid + i * 256] = make_uint2(0u, 0u);
        if (tid == 0) norms[row] = 1.0f;
        return;
    }
    const float4* s4 = reinterpret_cast<const float4*>(src + (size_t)row * DIM);
    float4 v[4]; float ssq = 0.0f;
    #pragma unroll
    for (int i = 0; i < 4; i++) {
        v[i] = s4[tid + i * 256];
        ssq += v[i].x*v[i].x + v[i].y*v[i].y + v[i].z*v[i].z + v[i].w*v[i].w;
    }
    #pragma unroll
    for (int o = 16; o > 0; o >>= 1) ssq += __shfl_down_sync(0xffffffffu, ssq, o);
    if (lid == 0) red[wid] = ssq;
    __syncthreads();
    if (tid == 0) {
        float t = 0.f;
        #pragma unroll
        for (int i = 0; i < 8; i++) t += red[i];
        red[0] = t;
    }
    __syncthreads();
    float norm = fmaxf(sqrtf(red[0]), 1e-8f);
    if (tid == 0) norms[row] = norm;
    float rn = 1.0f / norm;
    #pragma unroll
    for (int i = 0; i < 4; i++) {
        __half2 lo = __floats2half2_rn(v[i].x * rn, v[i].y * rn);
        __half2 hi = __floats2half2_rn(v[i].z * rn, v[i].w * rn);
        uint2 pk;
        pk.x = *reinterpret_cast<uint32_t*>(&lo);
        pk.y = *reinterpret_cast<uint32_t*>(&hi);
        drow[tid + i * 256] = pk;
    }
}

// ----- kernel 2: WMMA fp16 GEMM -> fp32 sims [m][v]; direct wmma store -----
__global__ __launch_bounds__(256) void lp_gemm()
{
    __shared__ __align__(32) __half smem[2 * (BM + BN) * APITCH];   // 40960 B
    __half* sA[2] = { smem,                smem + BM * APITCH };
    __half* sB[2] = { smem + 2*BM*APITCH,  smem + 2*BM*APITCH + BN * APITCH };

    const int tid = threadIdx.x, wid = tid >> 5;
    const int warpM = wid & 3;            // 4 warps over M (32 rows each)
    const int warpN = wid >> 2;           // 2 warps over N (64 cols each)
    const int mtile = blockIdx.x & 15;
    const int ntile = blockIdx.x >> 4;
    const size_t m_base = (size_t)mtile * BM;
    const size_t n_base = (size_t)ntile * BN;

    wmma::fragment<wmma::accumulator, 16, 16, 16, float> acc[2][4];
    #pragma unroll
    for (int mi = 0; mi < 2; mi++)
        #pragma unroll
        for (int ni = 0; ni < 4; ni++)
            wmma::fill_fragment(acc[mi][ni], 0.0f);

    // stage 0: direct global -> smem
    #pragma unroll
    for (int i = 0; i < 2; i++) {
        int g = tid + i * 256, r = g >> 2, c = g & 3;   // 4 x 16B per row
        *(float4*)&sA[0][r * APITCH + c * 8] =
            *(const float4*)(g_Ehf + (m_base + r) * DIM + c * 8);
        *(float4*)&sB[0][r * APITCH + c * 8] =
            *(const float4*)(g_Thf + (n_base + r) * DIM + c * 8);
    }
    __syncthreads();

    for (int ch = 0; ch < KCHUNKS; ch++) {
        const int cur = ch & 1, nxt = cur ^ 1;
        float4 pa[2], pb[2];
        if (ch + 1 < KCHUNKS) {
            #pragma unroll
            for (int i = 0; i < 2; i++) {
                int g = tid + i * 256, r = g >> 2, c = g & 3;
                pa[i] = *(const float4*)(g_Ehf + (m_base + r) * DIM +
                                         (size_t)(ch + 1) * BK + c * 8);
                pb[i] = *(const float4*)(g_Thf + (n_base + r) * DIM +
                                         (size_t)(ch + 1) * BK + c * 8);
            }
        }
        #pragma unroll
        for (int kk = 0; kk < 2; kk++) {
            wmma::fragment<wmma::matrix_a, 16,16,16, __half, wmma::row_major> af[2];
            wmma::fragment<wmma::matrix_b, 16,16,16, __half, wmma::col_major> bf[4];
            #pragma unroll
            for (int mi = 0; mi < 2; mi++)
                wmma::load_matrix_sync(af[mi],
                    &sA[cur][(warpM * 32 + mi * 16) * APITCH + kk * 16], APITCH);
            #pragma unroll
            for (int ni = 0; ni < 4; ni++)
                wmma::load_matrix_sync(bf[ni],
                    &sB[cur][(warpN * 64 + ni * 16) * APITCH + kk * 16], APITCH);
            #pragma unroll
            for (int mi = 0; mi < 2; mi++)
                #pragma unroll
                for (int ni = 0; ni < 4; ni++)
                    wmma::mma_sync(acc[mi][ni], af[mi], bf[ni], acc[mi][ni]);
        }
        if (ch + 1 < KCHUNKS) {
            #pragma unroll
            for (int i = 0; i < 2; i++) {
                int g = tid + i * 256, r = g >> 2, c = g & 3;
                *(float4*)&sA[nxt][r * APITCH + c * 8] = pa[i];
                *(float4*)&sB[nxt][r * APITCH + c * 8] = pb[i];
            }
        }
        __syncthreads();
    }

    // epilogue: direct WMMA store to global, row-major [m][v], ldm = V_PAD
    #pragma unroll
    for (int mi = 0; mi < 2; mi++)
        #pragma unroll
        for (int ni = 0; ni < 4; ni++)
            wmma::store_matrix_sync(
                g_simsf + (m_base + warpM * 32 + mi * 16) * (size_t)V_PAD
                        + n_base + warpN * 64 + ni * 16,
                acc[mi][ni], V_PAD, wmma::mem_row_major);
}

// ----- kernel 3: per-m argmax with inline fp64 rescore; float32 id output -----
__global__ __launch_bounds__(256) void lp_scan(const float* __restrict__ E,
                                               const float* __restrict__ T,
                                               float* __restrict__ out)
{
    const int m = blockIdx.x, t = threadIdx.x;
    const float* row = g_simsf + (size_t)m * V_PAD;

    // phase 1: block max over fp32 sims (coalesced)
    __shared__ float smax[256];
    float mx = -3.0e38f;
    for (int v = t; v < V_TOTAL; v += 256) mx = fmaxf(mx, row[v]);
    smax[t] = mx;
    __syncthreads();
    #pragma unroll
    for (int s = 128; s > 0; s >>= 1) {
        if (t < s) smax[t] = fmaxf(smax[t], smax[t + s]);
        __syncthreads();
    }
    const float thr = smax[0] - MARGIN;

    // phase 2: collect hits within margin (true argmax provably included)
    __shared__ int hits[256];
    __shared__ int nh;
    if (t == 0) nh = 0;
    __syncthreads();
    for (int v = t; v < V_TOTAL; v += 256) {
        if (row[v] >= thr) {
            int i = atomicAdd(&nh, 1);
            if (i < 256) hits[i] = v;
        }
    }
    __syncthreads();
    const int H = min(nh, 256);

    // phase 3: fp64 exact rescore of each hit, block-cooperative
    __shared__ double dred[256];
    __shared__ double bests;
    __shared__ int    bestv;
    if (t == 0) { bests = -1.0e300; bestv = 0; }
    __syncthreads();
    const float* e = E + (size_t)m * DIM;
    for (int h = 0; h < H; h++) {
        const int v = hits[h];
        const float* tv = T + (size_t)v * DIM;
        double s = 0.0;
        #pragma unroll 4
        for (int i = 0; i < 16; i++) {
            int d = t * 16 + i;
            s += (double)e[d] * (double)tv[d];
        }
        dred[t] = s;
        __syncthreads();
        #pragma unroll
        for (int st = 128; st > 0; st >>= 1) {
            if (t < st) dred[t] += dred[t + st];
            __syncthreads();
        }
        if (t == 0) {
            double sim = dred[0] / ((double)fmaxf(g_enorm[m], 1e-8f) *
                                    (double)fmaxf(g_tnorm[v], 1e-8f));
            if (sim > bests || (sim == bests && v < bestv)) { bests = sim; bestv = v; }
        }
        __syncthreads();
    }
    if (t == 0) out[m] = (float)bestv;     // float32 ids (proven dtype)
}

// ----- launch -----
extern "C" void kernel_launch(void* const* d_in, const int* in_sizes, int n_in,
                              void* d_out, int out_size) {
    const float* A0 = (const float*)d_in[0];
    const float* A1 = (const float*)d_in[1];
    const float* E = A0; const float* T = A1;             // metadata order
    if (in_sizes[0] != M_TOTAL * DIM) { E = A1; T = A0; }
    float* out = (float*)d_out;

    lp_normalize<<<M_TOTAL, 256>>>(E, M_TOTAL, 0);
    lp_normalize<<<V_PAD, 256>>>(T, V_TOTAL, 1);
    lp_gemm<<<M_TILES * N_TILES, 256>>>();
    lp_scan<<<M_TOTAL, 256>>>(E, T, out);
    (void)in_sizes; (void)n_in; (void)out_size;
}

// round 17
// speedup vs baseline: 114.6895x; 1.2031x over previous
#include <cuda_runtime.h>
#include <cuda_fp16.h>
#include <mma.h>
#include <cstdint>

using namespace nvcuda;

#define M_TOTAL   2048
#define V_TOTAL   50257
#define DIM       4096
#define BM        128
#define BN        256
#define BK        32
#define APITCH    40              // halves per smem row (64B data + 16B pad)
#define V_PAD     50432           // 197 * 256
#define N_TILES   197
#define M_TILES   16
#define KCHUNKS   128             // 4096 / 32
#define NSTAGE    3
#define STG_H     ((BM + BN) * APITCH)          // halves per stage: 15360
#define SMEM_BYTES (NSTAGE * STG_H * 2)         // 92160
#define MARGIN    2.5e-3f

// ----- device scratch (static; zero runtime allocation) -----
__device__ __align__(128) __half g_Ehf[(size_t)M_TOTAL * DIM];
__device__ __align__(128) __half g_Thf[(size_t)V_PAD * DIM];
__device__ __align__(128) float  g_simsf[(size_t)M_TOTAL * V_PAD];  // [m][v]
__device__ float g_enorm[M_TOTAL];
__device__ float g_tnorm[V_PAD];

__device__ __forceinline__ uint32_t smem_u32(const void* p) {
    uint32_t a;
    asm("{ .reg .u64 t; cvta.to.shared.u64 t, %1; cvt.u32.u64 %0, t; }" : "=r"(a) : "l"(p));
    return a;
}
__device__ __forceinline__ void cp16(uint32_t dst, const void* src) {
    asm volatile("cp.async.cg.shared.global [%0], [%1], 16;" :: "r"(dst), "l"(src));
}

// ----- kernel 1: normalize fp32 row -> unit fp16 row + fp32 norm -----
__global__ __launch_bounds__(256) void lp_normalize(
    const float* __restrict__ src, int n_valid, int which)
{
    __half* dstall = which ? g_Thf : g_Ehf;
    float*  norms  = which ? g_tnorm : g_enorm;
    int row = blockIdx.x, tid = threadIdx.x, wid = tid >> 5, lid = tid & 31;
    uint2* drow = reinterpret_cast<uint2*>(dstall + (size_t)row * DIM);
    __shared__ float red[8];
    if (row >= n_valid) {
        #pragma unroll
        for (int i = 0; i < 4; i++) drow[tid + i * 256] = make_uint2(0u, 0u);
        if (tid == 0) norms[row] = 1.0f;
        return;
    }
    const float4* s4 = reinterpret_cast<const float4*>(src + (size_t)row * DIM);
    float4 v[4]; float ssq = 0.0f;
    #pragma unroll
    for (int i = 0; i < 4; i++) {
        v[i] = s4[tid + i * 256];
        ssq += v[i].x*v[i].x + v[i].y*v[i].y + v[i].z*v[i].z + v[i].w*v[i].w;
    }
    #pragma unroll
    for (int o = 16; o > 0; o >>= 1) ssq += __shfl_down_sync(0xffffffffu, ssq, o);
    if (lid == 0) red[wid] = ssq;
    __syncthreads();
    if (tid == 0) {
        float t = 0.f;
        #pragma unroll
        for (int i = 0; i < 8; i++) t += red[i];
        red[0] = t;
    }
    __syncthreads();
    float norm = fmaxf(sqrtf(red[0]), 1e-8f);
    if (tid == 0) norms[row] = norm;
    float rn = 1.0f / norm;
    #pragma unroll
    for (int i = 0; i < 4; i++) {
        __half2 lo = __floats2half2_rn(v[i].x * rn, v[i].y * rn);
        __half2 hi = __floats2half2_rn(v[i].z * rn, v[i].w * rn);
        uint2 pk;
        pk.x = *reinterpret_cast<uint32_t*>(&lo);
        pk.y = *reinterpret_cast<uint32_t*>(&hi);
        drow[tid + i * 256] = pk;
    }
}

// ----- stage loader: 512 threads, cp.async, one commit per stage -----
__device__ __forceinline__ void load_stage(uint32_t sbase, int stage, int chunk,
                                           size_t m_base, size_t n_base, int tid)
{
    uint32_t sA = sbase + (uint32_t)stage * (STG_H * 2);
    uint32_t sB = sA + BM * APITCH * 2;
    const char* gA = (const char*)g_Ehf + (m_base * DIM + (size_t)chunk * BK) * 2;
    const char* gB = (const char*)g_Thf + (n_base * DIM + (size_t)chunk * BK) * 2;
    {   // A: 128 rows x 4 x 16B = 512 granules, 1 per thread
        int r = tid >> 2, c = tid & 3;
        cp16(sA + r * (APITCH * 2) + c * 16, gA + (size_t)r * (DIM * 2) + c * 16);
    }
    #pragma unroll
    for (int i = 0; i < 2; i++) {   // B: 256 rows x 4 x 16B = 1024 granules
        int idx = tid + i * 512, r = idx >> 2, c = idx & 3;
        cp16(sB + r * (APITCH * 2) + c * 16, gB + (size_t)r * (DIM * 2) + c * 16);
    }
    asm volatile("cp.async.commit_group;" ::: "memory");
}

// ----- kernel 2: WMMA fp16 GEMM (128x256x32, 3-stage cp.async) -----
__global__ __launch_bounds__(512) void lp_gemm()
{
    extern __shared__ __align__(16) __half smem[];
    const uint32_t sbase = smem_u32(smem);
    const int tid = threadIdx.x, wid = tid >> 5;
    const int warpM = wid & 3;            // 4 warps over M (32 rows)
    const int warpN = wid >> 2;           // 4 warps over N (64 cols)
    const int mtile = blockIdx.x & 15;
    const int ntile = blockIdx.x >> 4;
    const size_t m_base = (size_t)mtile * BM;
    const size_t n_base = (size_t)ntile * BN;

    wmma::fragment<wmma::accumulator, 16, 16, 16, float> acc[2][4];
    #pragma unroll
    for (int mi = 0; mi < 2; mi++)
        #pragma unroll
        for (int ni = 0; ni < 4; ni++)
            wmma::fill_fragment(acc[mi][ni], 0.0f);

    load_stage(sbase, 0, 0, m_base, n_base, tid);
    load_stage(sbase, 1, 1, m_base, n_base, tid);

    for (int ch = 0; ch < KCHUNKS; ch++) {
        asm volatile("cp.async.wait_group 1;" ::: "memory");   // stage ch ready
        __syncthreads();                                       // + stage (ch-1) fully consumed
        if (ch + 2 < KCHUNKS)
            load_stage(sbase, (ch + 2) % NSTAGE, ch + 2, m_base, n_base, tid);

        const int st = ch % NSTAGE;
        const __half* cA = smem + st * STG_H;
        const __half* cB = cA + BM * APITCH;
        #pragma unroll
        for (int kk = 0; kk < 2; kk++) {
            wmma::fragment<wmma::matrix_a, 16,16,16, __half, wmma::row_major> af[2];
            wmma::fragment<wmma::matrix_b, 16,16,16, __half, wmma::col_major> bf[4];
            #pragma unroll
            for (int mi = 0; mi < 2; mi++)
                wmma::load_matrix_sync(af[mi],
                    cA + (warpM * 32 + mi * 16) * APITCH + kk * 16, APITCH);
            #pragma unroll
            for (int ni = 0; ni < 4; ni++)
                wmma::load_matrix_sync(bf[ni],
                    cB + (warpN * 64 + ni * 16) * APITCH + kk * 16, APITCH);
            #pragma unroll
            for (int mi = 0; mi < 2; mi++)
                #pragma unroll
                for (int ni = 0; ni < 4; ni++)
                    wmma::mma_sync(acc[mi][ni], af[mi], bf[ni], acc[mi][ni]);
        }
    }

    // epilogue: direct WMMA store to global, row-major [m][v], ldm = V_PAD
    #pragma unroll
    for (int mi = 0; mi < 2; mi++)
        #pragma unroll
        for (int ni = 0; ni < 4; ni++)
            wmma::store_matrix_sync(
                g_simsf + (m_base + warpM * 32 + mi * 16) * (size_t)V_PAD
                        + n_base + warpN * 64 + ni * 16,
                acc[mi][ni], V_PAD, wmma::mem_row_major);
}

// ----- kernel 3: per-m argmax with inline fp64 rescore; float32 id output -----
__global__ __launch_bounds__(256) void lp_scan(const float* __restrict__ E,
                                               const float* __restrict__ T,
                                               float* __restrict__ out)
{
    const int m = blockIdx.x, t = threadIdx.x;
    const float* row = g_simsf + (size_t)m * V_PAD;

    __shared__ float smax[256];
    float mx = -3.0e38f;
    for (int v = t; v < V_TOTAL; v += 256) mx = fmaxf(mx, row[v]);
    smax[t] = mx;
    __syncthreads();
    #pragma unroll
    for (int s = 128; s > 0; s >>= 1) {
        if (t < s) smax[t] = fmaxf(smax[t], smax[t + s]);
        __syncthreads();
    }
    const float thr = smax[0] - MARGIN;

    __shared__ int hits[256];
    __shared__ int nh;
    if (t == 0) nh = 0;
    __syncthreads();
    for (int v = t; v < V_TOTAL; v += 256) {
        if (row[v] >= thr) {
            int i = atomicAdd(&nh, 1);
            if (i < 256) hits[i] = v;
        }
    }
    __syncthreads();
    const int H = min(nh, 256);

    __shared__ double dred[256];
    __shared__ double bests;
    __shared__ int    bestv;
    if (t == 0) { bests = -1.0e300; bestv = 0; }
    __syncthreads();
    const float* e = E + (size_t)m * DIM;
    for (int h = 0; h < H; h++) {
        const int v = hits[h];
        const float* tv = T + (size_t)v * DIM;
        double s = 0.0;
        #pragma unroll 4
        for (int i = 0; i < 16; i++) {
            int d = t * 16 + i;
            s += (double)e[d] * (double)tv[d];
        }
        dred[t] = s;
        __syncthreads();
        #pragma unroll
        for (int st = 128; st > 0; st >>= 1) {
            if (t < st) dred[t] += dred[t + st];
            __syncthreads();
        }
        if (t == 0) {
            double sim = dred[0] / ((double)fmaxf(g_enorm[m], 1e-8f) *
                                    (double)fmaxf(g_tnorm[v], 1e-8f));
            if (sim > bests || (sim == bests && v < bestv)) { bests = sim; bestv = v; }
        }
        __syncthreads();
    }
    if (t == 0) out[m] = (float)bestv;
}

// ----- launch -----
extern "C" void kernel_launch(void* const* d_in, const int* in_sizes, int n_in,
                              void* d_out, int out_size) {
    const float* A0 = (const float*)d_in[0];
    const float* A1 = (const float*)d_in[1];
    const float* E = A0; const float* T = A1;
    if (in_sizes[0] != M_TOTAL * DIM) { E = A1; T = A0; }
    float* out = (float*)d_out;

    cudaFuncSetAttribute(lp_gemm, cudaFuncAttributeMaxDynamicSharedMemorySize, SMEM_BYTES);

    lp_normalize<<<M_TOTAL, 256>>>(E, M_TOTAL, 0);
    lp_normalize<<<V_PAD, 256>>>(T, V_TOTAL, 1);
    lp_gemm<<<M_TILES * N_TILES, 512, SMEM_BYTES>>>();
    lp_scan<<<M_TOTAL, 256>>>(E, T, out);
    (void)in_sizes; (void)n_in; (void)out_size;
}